// round 7
// baseline (speedup 1.0000x reference)
#include <cuda_runtime.h>
#include <cuda_bf16.h>
#include <math.h>
#include <stdint.h>

// ---------------------------------------------------------------------------
// Problem constants
// ---------------------------------------------------------------------------
#define BATCH 512
#define MF    48
#define DD    128
#define O1    68
#define O2    32
#define O3    24
#define NPAIR 1176          // 48*49/2 symmetric pairs
#define KDIAG 1224          // + 48 linear (diag) rows
#define KPAD  1280          // padded to 20 tiles of 64
#define NG    144           // GEMM N: 68 xk1 + 4 pad + 68 R' + 4 pad
#define NKT   20            // k-tiles of 64
#define KT    64
#define TILEB (NG*KT*2)     // 18432 bytes per B tile
#define TILEP 16384         // P tile bytes per sample: 64 rows x 256B

// ---------------------------------------------------------------------------
// Device-global scratch (no allocation allowed)
// ---------------------------------------------------------------------------
__device__ unsigned int g_suv[KPAD];
__device__ __align__(16) __nv_bfloat16 g_Bt[NKT * NG * KT];  // packed+swizzled
__device__ float g_F[MF * MF * 64];                          // fc1 lookup

// ---------------------------------------------------------------------------
// Helpers
// ---------------------------------------------------------------------------
__device__ __forceinline__ void pair_decode(int t, int& u, int& v) {
    int k = 0, base = 0;
    while (t >= base + (MF - k)) { base += MF - k; ++k; }
    u = k; v = k + (t - base);
}

__device__ __forceinline__ uint32_t smem_u32(const void* p) {
    uint32_t a;
    asm("{ .reg .u64 t; cvta.to.shared.u64 t, %1; cvt.u32.u64 %0, t; }" : "=r"(a) : "l"(p));
    return a;
}

__device__ __forceinline__ uint32_t pack_bf16(float a, float b) {
    __nv_bfloat162 h = __floats2bfloat162_rn(a, b);   // a -> low, b -> high
    return *reinterpret_cast<uint32_t*>(&h);
}

__device__ __forceinline__ void ldsm_x4(uint32_t& r0, uint32_t& r1,
                                        uint32_t& r2, uint32_t& r3, uint32_t addr) {
    asm volatile("ldmatrix.sync.aligned.m8n8.x4.shared.b16 {%0,%1,%2,%3}, [%4];"
                 : "=r"(r0), "=r"(r1), "=r"(r2), "=r"(r3) : "r"(addr));
}

__device__ __forceinline__ void ldsm_x4_t(uint32_t& r0, uint32_t& r1,
                                          uint32_t& r2, uint32_t& r3, uint32_t addr) {
    asm volatile("ldmatrix.sync.aligned.m8n8.x4.trans.shared.b16 {%0,%1,%2,%3}, [%4];"
                 : "=r"(r0), "=r"(r1), "=r"(r2), "=r"(r3) : "r"(addr));
}

__device__ __forceinline__ void mma16816(float* c, uint32_t a0, uint32_t a1,
                                         uint32_t a2, uint32_t a3,
                                         uint32_t b0, uint32_t b1) {
    asm volatile(
        "mma.sync.aligned.m16n8k16.row.col.f32.bf16.bf16.f32 "
        "{%0,%1,%2,%3}, {%4,%5,%6,%7}, {%8,%9}, {%0,%1,%2,%3};"
        : "+f"(c[0]), "+f"(c[1]), "+f"(c[2]), "+f"(c[3])
        : "r"(a0), "r"(a1), "r"(a2), "r"(a3), "r"(b0), "r"(b1));
}

// ---------------------------------------------------------------------------
// Single prep kernel, 918 blocks:
//   [0,6):     suv table
//   [6,198):   F = fc1 lookup table, block = (j, m-quarter), smem-tiled
//   [198,918): B pack (each block computes its own V3 slice in smem)
// ---------------------------------------------------------------------------
__global__ void prep_all(const float* __restrict__ w1, const float* __restrict__ w2,
                         const float* __restrict__ w3, const float* __restrict__ out_w,
                         const float* __restrict__ emb, const float* __restrict__ fc1_w) {
    __shared__ float sf[1536 + 8192];   // 38.9KB, reused per-branch
    const int tid = threadIdx.x;
    const int b   = blockIdx.x;

    if (b < 6) {
        int gid = b * 256 + tid;
        if (gid < KPAD) {
            int u, v;
            if (gid < NPAIR)      { pair_decode(gid, u, v); }
            else if (gid < KDIAG) { u = gid - NPAIR; v = 48; }
            else                  { u = 49; v = 49; }
            g_suv[gid] = (unsigned)u | ((unsigned)v << 16);
        }
        return;
    }

    if (b < 198) {
        // F table: j = field, q = m-quarter (12 rows)
        const int fb = b - 6;
        const int j = fb >> 2, q = fb & 3;
        float* se = sf;            // emb rows q*12..q*12+11  (1536 floats)
        float* sw = sf + 1536;     // fc1_w slice j           (8192 floats)
        for (int i = tid; i < 1536; i += 256) se[i] = emb[q * 1536 + i];
        for (int i = tid; i < 8192; i += 256) sw[i] = fc1_w[j * 8192 + i];
        __syncthreads();
        #pragma unroll
        for (int t = 0; t < 3; ++t) {
            int o = t * 256 + tid;           // < 768
            int m = o >> 6, c = o & 63;
            float s = 0.f;
            #pragma unroll 8
            for (int d = 0; d < DD; ++d) s += se[m * DD + d] * sw[d * 64 + c];
            g_F[((j * MF + q * 12 + m) << 6) + c] = s;
        }
        return;
    }

    // ---- B pack ----
    float* sV = sf;                          // 1536 floats
    for (int i = tid; i < O2 * MF; i += 256) {
        float s = 0.f;
        #pragma unroll
        for (int o = 0; o < O3; ++o) s += w3[i * O3 + o] * out_w[125 + o];
        sV[i] = s;
    }
    __syncthreads();

    int idx = (b - 198) * 256 + tid;         // < NKT*NG*KT = 184320
    int t = idx / (NG * KT);
    int r = idx - t * (NG * KT);
    int n = r >> 6, kk = r & 63;
    int k = t * 64 + kk;
    float val = 0.f;
    if (n < O1) {
        if (k < NPAIR) {
            int u, v; pair_decode(k, u, v);
            val = w1[(u * MF + v) * O1 + n];
            if (u < v) val += w1[(v * MF + u) * O1 + n];
        }
    } else if (n >= 72 && n < 72 + O1) {
        int a = n - 72;
        if (k < NPAIR) {
            int u, v; pair_decode(k, u, v);
            float s = 0.f;
            const float* r1 = w2 + (a * MF + u) * O2;
            #pragma unroll 8
            for (int k2 = 0; k2 < O2; ++k2) s += r1[k2] * sV[k2 * MF + v];
            if (u < v) {
                const float* r2 = w2 + (a * MF + v) * O2;
                #pragma unroll 8
                for (int k2 = 0; k2 < O2; ++k2) s += r2[k2] * sV[k2 * MF + u];
            }
            val = s;
        } else if (k < KDIAG) {
            int m = k - NPAIR;
            float s = 0.f;
            const float* r1 = w2 + (a * MF + m) * O2;
            #pragma unroll 8
            for (int k2 = 0; k2 < O2; ++k2) s += r1[k2] * out_w[25 + O1 + k2];
            val = s;
        }
    }
    int chunk = kk >> 3;
    int off = t * TILEB + n * 128 + ((chunk ^ (n & 7)) << 4) + ((kk & 7) << 1);
    *(__nv_bfloat16*)((char*)g_Bt + off) = __float2bfloat16_rn(val);
}

// ---------------------------------------------------------------------------
// Main fused kernel: one CTA per TWO batch rows.
// P tiles generated cooperatively (vectorized, conflict-free) into smem,
// A fragments via ldmatrix.x4.trans, B via ldmatrix.x4; software-pipelined.
// ---------------------------------------------------------------------------
// dyn smem layout (bytes, from 1024-aligned base)
#define OFF_X0R   0                    // 2 * 50*128 f32 = 51200 (rows 48=1, 49=0)
#define OFF_B     51200                // 2 * 18432 = 36864
#define OFF_P     88064                // 2 bufs * 2 smp * 16384 = 65536
#define OFF_SUV   153600               // 1280 u32 = 5120
#define OFF_OWP   158720               // 144 f32  = 576
#define OFF_XR    159296               // 2*48 int = 384
#define OFF_D1    159680               // 2*64 f32
#define OFF_D2    160192               // 2*48 f32
#define OFF_D3    160576               // 2*24 f32
#define OFF_RED   160768               // 2*8 f32
#define SMEM_DYN  (160832 + 1024)

__global__ __launch_bounds__(256, 1) void cin_main(
    const int*   __restrict__ x,     const float* __restrict__ emb,
    const float* __restrict__ lin_w, const float* __restrict__ lin_b,
    const float* __restrict__ fc1_b,
    const float* __restrict__ bn1_g, const float* __restrict__ bn1_b,
    const float* __restrict__ fc2_w, const float* __restrict__ fc2_b,
    const float* __restrict__ bn2_g, const float* __restrict__ bn2_b,
    const float* __restrict__ fc3_w, const float* __restrict__ fc3_b,
    const float* __restrict__ bn3_g, const float* __restrict__ bn3_b,
    const float* __restrict__ out_w, const float* __restrict__ out_b,
    float* __restrict__ out)
{
    extern __shared__ char smraw[];
    char* sm = (char*)(((uintptr_t)smraw + 1023) & ~(uintptr_t)1023);
    float*        x0r  = (float*)(sm + OFF_X0R);    // [2][50][128]
    unsigned int* ssuv = (unsigned int*)(sm + OFF_SUV);
    float*        owp  = (float*)(sm + OFF_OWP);
    int*          xr   = (int*)(sm + OFF_XR);
    float*        d1s  = (float*)(sm + OFF_D1);
    float*        d2s  = (float*)(sm + OFF_D2);
    float*        d3s  = (float*)(sm + OFF_D3);
    float*        red  = (float*)(sm + OFF_RED);

    const int tid  = threadIdx.x;
    const int lane = tid & 31;
    const int warp = tid >> 5;
    const uint32_t s32 = smem_u32(sm);

    if (tid < 2 * MF) xr[tid] = x[blockIdx.x * (2 * MF) + tid];
    for (int i = tid; i < NG; i += 256) owp[i] = (i < O1) ? out_w[25 + i] : 0.f;
    for (int i = tid; i < KPAD; i += 256) ssuv[i] = g_suv[i];
    __syncthreads();

    // gather x0 row-major with sentinel rows: x0r[smp][j][d], j48=1.0, j49=0.0
    for (int i = tid; i < 2 * 50 * DD; i += 256) {
        int smp = i / 6400;
        int rr  = i - smp * 6400;
        int j = rr >> 7, d = rr & 127;
        float v;
        if (j < MF)       v = emb[(xr[smp * MF + j] << 7) + d];
        else if (j == 48) v = 1.0f;
        else              v = 0.0f;
        x0r[i] = v;
    }
    __syncthreads();   // x0r ready before gen

    // ---- P tile generator: tile t -> buffer nb ----
    auto genP = [&](int t, int nb) {
        char* Pb = sm + OFF_P + nb * (2 * TILEP);
        #pragma unroll 4
        for (int it = 0; it < 16; ++it) {
            int task = it * 256 + tid;           // < 4096
            int dg  = task & 31;
            int kk  = (task >> 5) & 63;
            int smp = task >> 11;
            unsigned p = ssuv[t * 64 + kk];
            int u = p & 0xFFFF, v = p >> 16;
            const float4 xu = *(const float4*)(x0r + smp * 6400 + (u << 7) + (dg << 2));
            const float4 xv = *(const float4*)(x0r + smp * 6400 + (v << 7) + (dg << 2));
            uint32_t lo = pack_bf16(xu.x * xv.x, xu.y * xv.y);
            uint32_t hi = pack_bf16(xu.z * xv.z, xu.w * xv.w);
            char* dst = Pb + smp * TILEP + (kk << 8)
                        + ((((dg >> 1) ^ (kk & 7))) << 4) + ((dg & 1) << 3);
            *(uint2*)dst = make_uint2(lo, hi);
        }
    };
    auto stageB = [&](int t, int nb) {
        const uint4* src = (const uint4*)((const char*)g_Bt + t * TILEB);
        uint4* dst = (uint4*)(sm + OFF_B + nb * TILEB);
        for (int i = tid; i < TILEB / 16; i += 256) dst[i] = src[i];
    };

    // prologue
    stageB(0, 0);
    genP(0, 0);
    __syncthreads();

    // fragment geometry
    const int kq    = (lane & 3) << 1;                    // epilogue col offset
    const int matq  = lane >> 3;
    const int nloc  = ((matq >= 2) ? 8 : 0) + (lane & 7); // B lane row
    const int cksel = matq & 1;                           // B k-chunk select
    const int arow  = (lane & 7) + ((lane >> 4) << 3);    // A lane k-row (0..15)
    const int ach   = warp * 2 + ((lane >> 3) & 1);       // A m-chunk (16B units)

    float accA[18][4], accB[18][4];
    #pragma unroll
    for (int i = 0; i < 18; ++i)
        #pragma unroll
        for (int r = 0; r < 4; ++r) { accA[i][r] = 0.f; accB[i][r] = 0.f; }

    for (int t = 0; t < NKT; ++t) {
        const int buf = t & 1;
        if (t < NKT - 1) {
            stageB(t + 1, buf ^ 1);
            genP(t + 1, buf ^ 1);
        }
        const uint32_t Bb = s32 + OFF_B + buf * TILEB;
        const uint32_t Pb = s32 + OFF_P + buf * (2 * TILEP);

        #pragma unroll
        for (int s = 0; s < 4; ++s) {
            const int ks = s << 4;
            const int krow = ks + arow;
            const uint32_t asw = (uint32_t)((ach ^ (krow & 7)) << 4);
            uint32_t a0, a1, a2, a3, c0, c1, c2, c3;
            ldsm_x4_t(a0, a1, a2, a3, Pb + (krow << 8) + asw);
            ldsm_x4_t(c0, c1, c2, c3, Pb + TILEP + (krow << 8) + asw);

            const int chunk = (ks >> 3) + cksel;
            #pragma unroll
            for (int q = 0; q < 9; ++q) {
                const int n = q * 16 + nloc;
                uint32_t baddr = Bb + n * 128 + (uint32_t)((chunk ^ (n & 7)) << 4);
                uint32_t b0, b1, b2, b3;
                ldsm_x4(b0, b1, b2, b3, baddr);
                mma16816(accA[2 * q],     a0, a1, a2, a3, b0, b1);
                mma16816(accA[2 * q + 1], a0, a1, a2, a3, b2, b3);
                mma16816(accB[2 * q],     c0, c1, c2, c3, b0, b1);
                mma16816(accB[2 * q + 1], c0, c1, c2, c3, b2, b3);
            }
        }
        __syncthreads();
    }

    // ---- epilogue straight from accumulator registers ----
    float partA = 0.f, partB = 0.f;
    #pragma unroll
    for (int nt = 0; nt < 9; ++nt) {
        const float w0 = owp[nt * 8 + kq];
        const float w1v = owp[nt * 8 + kq + 1];
        #pragma unroll
        for (int r = 0; r < 4; ++r) {
            float wv = (r & 1) ? w1v : w0;
            float xa = accA[nt][r];
            partA += xa * accA[nt + 9][r] + wv * xa;
            float xb = accB[nt][r];
            partB += xb * accB[nt + 9][r] + wv * xb;
        }
    }
    #pragma unroll
    for (int off = 16; off; off >>= 1) {
        partA += __shfl_xor_sync(0xffffffffu, partA, off);
        partB += __shfl_xor_sync(0xffffffffu, partB, off);
    }
    if (lane == 0) { red[warp] = partA; red[8 + warp] = partB; }

    // ---- deep MLP (fp32 exact): half-block per sample ----
    const int smp = tid >> 7;
    const int t1  = tid & 127;
    const int* xrs = xr + smp * MF;
    const float invs = rsqrtf(1.0f + 1e-3f);
    __syncthreads();
    if (t1 < 64) {
        float a = fc1_b[t1];
        #pragma unroll
        for (int j = 0; j < MF; ++j) a += g_F[((j * MF + xrs[j]) << 6) + t1];
        a = fmaxf(a, 0.f);
        d1s[smp * 64 + t1] = bn1_g[t1] * a * invs + bn1_b[t1];
    }
    __syncthreads();
    if (t1 < 48) {
        float a = fc2_b[t1];
        const float* d1 = d1s + smp * 64;
        #pragma unroll 8
        for (int i = 0; i < 64; ++i) a += d1[i] * fc2_w[i * 48 + t1];
        a = tanhf(a);
        d2s[smp * 48 + t1] = bn2_g[t1] * a * invs + bn2_b[t1];
    }
    __syncthreads();
    if (t1 < 24) {
        float a = fc3_b[t1];
        const float* d2 = d2s + smp * 48;
        #pragma unroll 8
        for (int i = 0; i < 48; ++i) a += d2[i] * fc3_w[i * 24 + t1];
        a = tanhf(a);
        d3s[smp * 24 + t1] = bn3_g[t1] * a * invs + bn3_b[t1];
    }
    __syncthreads();

    if (t1 == 0) {
        float lg = out_b[0];
        #pragma unroll
        for (int w = 0; w < 8; ++w) lg += red[smp * 8 + w];
        const float* d3 = d3s + smp * 24;
        #pragma unroll
        for (int c = 0; c < 24; ++c) lg += d3[c] * out_w[c];
        float sl = lin_b[0];
        #pragma unroll
        for (int j = 0; j < MF; ++j) sl += (float)xrs[j] * lin_w[j];
        lg += tanhf(sl) * out_w[24];
        out[blockIdx.x * 2 + smp] = 1.0f / (1.0f + expf(-lg));
    }
}

// ---------------------------------------------------------------------------
// Launch
// ---------------------------------------------------------------------------
extern "C" void kernel_launch(void* const* d_in, const int* in_sizes, int n_in,
                              void* d_out, int out_size)
{
    const int*   x     = (const int*)  d_in[0];
    const float* emb   = (const float*)d_in[1];
    const float* w1    = (const float*)d_in[2];
    const float* w2    = (const float*)d_in[3];
    const float* w3    = (const float*)d_in[4];
    const float* lin_w = (const float*)d_in[5];
    const float* lin_b = (const float*)d_in[6];
    const float* fc1_w = (const float*)d_in[7];
    const float* fc1_b = (const float*)d_in[8];
    const float* bn1_g = (const float*)d_in[9];
    const float* bn1_b = (const float*)d_in[10];
    const float* fc2_w = (const float*)d_in[11];
    const float* fc2_b = (const float*)d_in[12];
    const float* bn2_g = (const float*)d_in[13];
    const float* bn2_b = (const float*)d_in[14];
    const float* fc3_w = (const float*)d_in[15];
    const float* fc3_b = (const float*)d_in[16];
    const float* bn3_g = (const float*)d_in[17];
    const float* bn3_b = (const float*)d_in[18];
    const float* out_w = (const float*)d_in[19];
    const float* out_b = (const float*)d_in[20];
    float* out = (float*)d_out;

    prep_all<<<918, 256>>>(w1, w2, w3, out_w, emb, fc1_w);

    cudaFuncSetAttribute(cin_main, cudaFuncAttributeMaxDynamicSharedMemorySize, SMEM_DYN);
    cin_main<<<BATCH / 2, 256, SMEM_DYN>>>(
        x, emb, lin_w, lin_b, fc1_b, bn1_g, bn1_b,
        fc2_w, fc2_b, bn2_g, bn2_b, fc3_w, fc3_b, bn3_g, bn3_b,
        out_w, out_b, out);
}

// round 8
// speedup vs baseline: 1.1498x; 1.1498x over previous
#include <cuda_runtime.h>
#include <cuda_bf16.h>
#include <math.h>
#include <stdint.h>

// ---------------------------------------------------------------------------
// Problem constants
// ---------------------------------------------------------------------------
#define BATCH 512
#define MF    48
#define DD    128
#define O1    68
#define O2    32
#define O3    24
#define NPAIR 1176          // 48*49/2 symmetric pairs
#define KDIAG 1224          // + 48 linear (diag) rows
#define KPAD  1280          // padded to 20 tiles of 64
#define NG    144           // GEMM N: 68 xk1 + 4 pad + 68 R' + 4 pad
#define NKT   20            // k-tiles of 64
#define KT    64
#define TILEB (NG*KT*2)     // 18432 bytes per B tile
#define XST   50            // x0t row stride (48 data + 1.0 + 0.0)
#define NTHR  512

// ---------------------------------------------------------------------------
// Device-global scratch (no allocation allowed)
// ---------------------------------------------------------------------------
__device__ unsigned int g_suv[KPAD];
__device__ __align__(16) __nv_bfloat16 g_Bt[NKT * NG * KT];  // packed+swizzled
__device__ float g_F[MF * MF * 64];                          // fc1 lookup

// ---------------------------------------------------------------------------
// Helpers
// ---------------------------------------------------------------------------
__device__ __forceinline__ void pair_decode(int t, int& u, int& v) {
    int k = 0, base = 0;
    while (t >= base + (MF - k)) { base += MF - k; ++k; }
    u = k; v = k + (t - base);
}

__device__ __forceinline__ uint32_t smem_u32(const void* p) {
    uint32_t a;
    asm("{ .reg .u64 t; cvta.to.shared.u64 t, %1; cvt.u32.u64 %0, t; }" : "=r"(a) : "l"(p));
    return a;
}

__device__ __forceinline__ uint32_t pack_bf16(float a, float b) {
    __nv_bfloat162 h = __floats2bfloat162_rn(a, b);   // a -> low, b -> high
    return *reinterpret_cast<uint32_t*>(&h);
}

__device__ __forceinline__ void ldsm_x4(uint32_t& r0, uint32_t& r1,
                                        uint32_t& r2, uint32_t& r3, uint32_t addr) {
    asm volatile("ldmatrix.sync.aligned.m8n8.x4.shared.b16 {%0,%1,%2,%3}, [%4];"
                 : "=r"(r0), "=r"(r1), "=r"(r2), "=r"(r3) : "r"(addr));
}

__device__ __forceinline__ void mma16816(float* c, uint32_t a0, uint32_t a1,
                                         uint32_t a2, uint32_t a3,
                                         uint32_t b0, uint32_t b1) {
    asm volatile(
        "mma.sync.aligned.m16n8k16.row.col.f32.bf16.bf16.f32 "
        "{%0,%1,%2,%3}, {%4,%5,%6,%7}, {%8,%9}, {%0,%1,%2,%3};"
        : "+f"(c[0]), "+f"(c[1]), "+f"(c[2]), "+f"(c[3])
        : "r"(a0), "r"(a1), "r"(a2), "r"(a3), "r"(b0), "r"(b1));
}

__device__ __forceinline__ void cp16(uint32_t dst, const void* src) {
    asm volatile("cp.async.cg.shared.global [%0], [%1], 16;" :: "r"(dst), "l"(src));
}
#define CP_COMMIT() asm volatile("cp.async.commit_group;" ::: "memory")
#define CP_WAIT0()  asm volatile("cp.async.wait_group 0;" ::: "memory")

// ---------------------------------------------------------------------------
// Single prep kernel, 918 blocks:
//   [0,6):     suv table
//   [6,198):   F = fc1 lookup table, block = (j, m-quarter), smem-tiled
//   [198,918): B pack (each block computes its own V3 slice in smem)
// ---------------------------------------------------------------------------
__global__ void prep_all(const float* __restrict__ w1, const float* __restrict__ w2,
                         const float* __restrict__ w3, const float* __restrict__ out_w,
                         const float* __restrict__ emb, const float* __restrict__ fc1_w) {
    __shared__ float sf[1536 + 8192];
    const int tid = threadIdx.x;
    const int b   = blockIdx.x;

    if (b < 6) {
        int gid = b * 256 + tid;
        if (gid < KPAD) {
            int u, v;
            if (gid < NPAIR)      { pair_decode(gid, u, v); }
            else if (gid < KDIAG) { u = gid - NPAIR; v = 48; }
            else                  { u = 49; v = 49; }
            g_suv[gid] = (unsigned)u | ((unsigned)v << 16);
        }
        return;
    }

    if (b < 198) {
        const int fb = b - 6;
        const int j = fb >> 2, q = fb & 3;
        float* se = sf;
        float* sw = sf + 1536;
        for (int i = tid; i < 1536; i += 256) se[i] = emb[q * 1536 + i];
        for (int i = tid; i < 8192; i += 256) sw[i] = fc1_w[j * 8192 + i];
        __syncthreads();
        #pragma unroll
        for (int t = 0; t < 3; ++t) {
            int o = t * 256 + tid;
            int m = o >> 6, c = o & 63;
            float s = 0.f;
            #pragma unroll 8
            for (int d = 0; d < DD; ++d) s += se[m * DD + d] * sw[d * 64 + c];
            g_F[((j * MF + q * 12 + m) << 6) + c] = s;
        }
        return;
    }

    float* sV = sf;
    for (int i = tid; i < O2 * MF; i += 256) {
        float s = 0.f;
        #pragma unroll
        for (int o = 0; o < O3; ++o) s += w3[i * O3 + o] * out_w[125 + o];
        sV[i] = s;
    }
    __syncthreads();

    int idx = (b - 198) * 256 + tid;
    int t = idx / (NG * KT);
    int r = idx - t * (NG * KT);
    int n = r >> 6, kk = r & 63;
    int k = t * 64 + kk;
    float val = 0.f;
    if (n < O1) {
        if (k < NPAIR) {
            int u, v; pair_decode(k, u, v);
            val = w1[(u * MF + v) * O1 + n];
            if (u < v) val += w1[(v * MF + u) * O1 + n];
        }
    } else if (n >= 72 && n < 72 + O1) {
        int a = n - 72;
        if (k < NPAIR) {
            int u, v; pair_decode(k, u, v);
            float s = 0.f;
            const float* r1 = w2 + (a * MF + u) * O2;
            #pragma unroll 8
            for (int k2 = 0; k2 < O2; ++k2) s += r1[k2] * sV[k2 * MF + v];
            if (u < v) {
                const float* r2 = w2 + (a * MF + v) * O2;
                #pragma unroll 8
                for (int k2 = 0; k2 < O2; ++k2) s += r2[k2] * sV[k2 * MF + u];
            }
            val = s;
        } else if (k < KDIAG) {
            int m = k - NPAIR;
            float s = 0.f;
            const float* r1 = w2 + (a * MF + m) * O2;
            #pragma unroll 8
            for (int k2 = 0; k2 < O2; ++k2) s += r1[k2] * out_w[25 + O1 + k2];
            val = s;
        }
    }
    int chunk = kk >> 3;
    int off = t * TILEB + n * 128 + ((chunk ^ (n & 7)) << 4) + ((kk & 7) << 1);
    *(__nv_bfloat16*)((char*)g_Bt + off) = __float2bfloat16_rn(val);
}

// ---------------------------------------------------------------------------
// Main fused kernel: one CTA per TWO batch rows, 512 threads / 16 warps.
// Warp w: m-tile (w>>1) of sample (w&1). 72 acc floats/thread -> <=128 regs.
// B staged via cp.async double buffer; A fragments generated inline in regs.
// ---------------------------------------------------------------------------
// dyn smem layout (bytes, from 1024-aligned base)
#define OFF_X0T   0                    // 2 * 128*50 f32 = 51200
#define OFF_B     51200                // 2 * 18432 = 36864
#define OFF_SUV   88064                // 1280 u32  = 5120
#define OFF_OWP   93184                // 144 f32   = 576
#define OFF_XR    93760                // 2*48 int  = 384
#define OFF_D1    94144                // 2*64 f32
#define OFF_D2    94656                // 2*48 f32
#define OFF_D3    95040                // 2*24 f32
#define OFF_RED   95232                // 16 f32
#define SMEM_DYN  (95296 + 1024)

__global__ __launch_bounds__(NTHR, 1) void cin_main(
    const int*   __restrict__ x,     const float* __restrict__ emb,
    const float* __restrict__ lin_w, const float* __restrict__ lin_b,
    const float* __restrict__ fc1_b,
    const float* __restrict__ bn1_g, const float* __restrict__ bn1_b,
    const float* __restrict__ fc2_w, const float* __restrict__ fc2_b,
    const float* __restrict__ bn2_g, const float* __restrict__ bn2_b,
    const float* __restrict__ fc3_w, const float* __restrict__ fc3_b,
    const float* __restrict__ bn3_g, const float* __restrict__ bn3_b,
    const float* __restrict__ out_w, const float* __restrict__ out_b,
    float* __restrict__ out)
{
    extern __shared__ char smraw[];
    char* sm = (char*)(((uintptr_t)smraw + 1023) & ~(uintptr_t)1023);
    float*        x0t  = (float*)(sm + OFF_X0T);    // [2][128][50]
    unsigned int* ssuv = (unsigned int*)(sm + OFF_SUV);
    float*        owp  = (float*)(sm + OFF_OWP);
    int*          xr   = (int*)(sm + OFF_XR);
    float*        d1s  = (float*)(sm + OFF_D1);
    float*        d2s  = (float*)(sm + OFF_D2);
    float*        d3s  = (float*)(sm + OFF_D3);
    float*        red  = (float*)(sm + OFF_RED);

    const int tid  = threadIdx.x;
    const int lane = tid & 31;
    const int warp = tid >> 5;       // 0..15
    const uint32_t s32 = smem_u32(sm);

    if (tid < 2 * MF) xr[tid] = x[blockIdx.x * (2 * MF) + tid];
    for (int i = tid; i < NG; i += NTHR) owp[i] = (i < O1) ? out_w[25 + i] : 0.f;
    for (int i = tid; i < KPAD; i += NTHR) ssuv[i] = g_suv[i];
    __syncthreads();

    // gather both samples' x0 transposed with sentinels: x0t[smp*6400 + d*50 + j]
    for (int i = tid; i < 2 * DD * XST; i += NTHR) {
        int smp = i / (DD * XST);
        int rr  = i - smp * (DD * XST);
        int d = rr / XST, j = rr - d * XST;
        float v;
        if (j < MF)       v = emb[(xr[smp * MF + j] << 7) + d];
        else if (j == 48) v = 1.0f;
        else              v = 0.0f;
        x0t[i] = v;
    }

    // prologue: cp.async B tile 0 into buf0
    for (int i = tid; i < TILEB / 16; i += NTHR)
        cp16(s32 + OFF_B + i * 16, (const char*)g_Bt + i * 16);
    CP_COMMIT();
    CP_WAIT0();
    __syncthreads();

    // per-warp fragment geometry: m-tile = warp>>1, sample = warp&1
    const int wsmp  = warp & 1;
    const int rbase = wsmp * 6400 + (((warp >> 1) * 16) + (lane >> 2)) * XST;
    const float* rA0 = x0t + rbase;
    const float* rA1 = rA0 + 8 * XST;
    const int kq    = (lane & 3) << 1;
    const int matq  = lane >> 3;
    const int nloc  = ((matq >= 2) ? 8 : 0) + (lane & 7);
    const int cksel = matq & 1;

    float acc[18][4];
    #pragma unroll
    for (int i = 0; i < 18; ++i)
        #pragma unroll
        for (int r = 0; r < 4; ++r) acc[i][r] = 0.f;

    for (int t = 0; t < NKT; ++t) {
        const int buf = t & 1;
        if (t < NKT - 1) {
            const char* src = (const char*)g_Bt + (t + 1) * TILEB;
            uint32_t dst = s32 + OFF_B + (buf ^ 1) * TILEB;
            for (int i = tid; i < TILEB / 16; i += NTHR)
                cp16(dst + i * 16, src + i * 16);
            CP_COMMIT();
        }
        const uint32_t Bb = s32 + OFF_B + buf * TILEB;
        const int k0 = t * 64;

        #pragma unroll
        for (int s = 0; s < 4; ++s) {
            const int ks = s << 4;
            const int kg = k0 + ks + kq;
            unsigned p0 = ssuv[kg],     p1 = ssuv[kg + 1];
            unsigned p8 = ssuv[kg + 8], p9 = ssuv[kg + 9];
            const int u0 = p0 & 0xFFFF, w0i = p0 >> 16;
            const int u1 = p1 & 0xFFFF, w1i = p1 >> 16;
            const int u8 = p8 & 0xFFFF, w8i = p8 >> 16;
            const int u9 = p9 & 0xFFFF, w9i = p9 >> 16;
            uint32_t a0 = pack_bf16(rA0[u0] * rA0[w0i], rA0[u1] * rA0[w1i]);
            uint32_t a1 = pack_bf16(rA1[u0] * rA1[w0i], rA1[u1] * rA1[w1i]);
            uint32_t a2 = pack_bf16(rA0[u8] * rA0[w8i], rA0[u9] * rA0[w9i]);
            uint32_t a3 = pack_bf16(rA1[u8] * rA1[w8i], rA1[u9] * rA1[w9i]);

            const int chunk = (ks >> 3) + cksel;
            #pragma unroll
            for (int q = 0; q < 9; ++q) {
                const int n = q * 16 + nloc;
                uint32_t baddr = Bb + n * 128 + (uint32_t)((chunk ^ (n & 7)) << 4);
                uint32_t b0, b1, b2, b3;
                ldsm_x4(b0, b1, b2, b3, baddr);
                mma16816(acc[2 * q],     a0, a1, a2, a3, b0, b1);
                mma16816(acc[2 * q + 1], a0, a1, a2, a3, b2, b3);
            }
        }
        if (t < NKT - 1) CP_WAIT0();
        __syncthreads();
    }

    // ---- epilogue straight from accumulator registers ----
    float part = 0.f;
    #pragma unroll
    for (int nt = 0; nt < 9; ++nt) {
        const float w0 = owp[nt * 8 + kq];
        const float w1v = owp[nt * 8 + kq + 1];
        #pragma unroll
        for (int r = 0; r < 4; ++r) {
            float wv = (r & 1) ? w1v : w0;
            float xa = acc[nt][r];
            part += xa * acc[nt + 9][r] + wv * xa;
        }
    }
    #pragma unroll
    for (int off = 16; off; off >>= 1)
        part += __shfl_xor_sync(0xffffffffu, part, off);
    if (lane == 0) red[warp] = part;

    // ---- deep MLP (fp32 exact): half-block per sample ----
    const int smp = tid >> 8;        // 0 or 1
    const int t1  = tid & 255;
    const int* xrs = xr + smp * MF;
    const float invs = rsqrtf(1.0f + 1e-3f);
    __syncthreads();
    if (t1 < 64) {
        float a = fc1_b[t1];
        #pragma unroll
        for (int j = 0; j < MF; ++j) a += g_F[((j * MF + xrs[j]) << 6) + t1];
        a = fmaxf(a, 0.f);
        d1s[smp * 64 + t1] = bn1_g[t1] * a * invs + bn1_b[t1];
    }
    __syncthreads();
    if (t1 < 48) {
        float a = fc2_b[t1];
        const float* d1 = d1s + smp * 64;
        #pragma unroll 8
        for (int i = 0; i < 64; ++i) a += d1[i] * fc2_w[i * 48 + t1];
        a = tanhf(a);
        d2s[smp * 48 + t1] = bn2_g[t1] * a * invs + bn2_b[t1];
    }
    __syncthreads();
    if (t1 < 24) {
        float a = fc3_b[t1];
        const float* d2 = d2s + smp * 48;
        #pragma unroll 8
        for (int i = 0; i < 48; ++i) a += d2[i] * fc3_w[i * 24 + t1];
        a = tanhf(a);
        d3s[smp * 24 + t1] = bn3_g[t1] * a * invs + bn3_b[t1];
    }
    __syncthreads();

    if (t1 == 0) {
        float lg = out_b[0];
        #pragma unroll
        for (int w = 0; w < 8; ++w) lg += red[2 * w + smp];   // warps of this sample
        const float* d3 = d3s + smp * 24;
        #pragma unroll
        for (int c = 0; c < 24; ++c) lg += d3[c] * out_w[c];
        float sl = lin_b[0];
        #pragma unroll
        for (int j = 0; j < MF; ++j) sl += (float)xrs[j] * lin_w[j];
        lg += tanhf(sl) * out_w[24];
        out[blockIdx.x * 2 + smp] = 1.0f / (1.0f + expf(-lg));
    }
}

// ---------------------------------------------------------------------------
// Launch
// ---------------------------------------------------------------------------
extern "C" void kernel_launch(void* const* d_in, const int* in_sizes, int n_in,
                              void* d_out, int out_size)
{
    const int*   x     = (const int*)  d_in[0];
    const float* emb   = (const float*)d_in[1];
    const float* w1    = (const float*)d_in[2];
    const float* w2    = (const float*)d_in[3];
    const float* w3    = (const float*)d_in[4];
    const float* lin_w = (const float*)d_in[5];
    const float* lin_b = (const float*)d_in[6];
    const float* fc1_w = (const float*)d_in[7];
    const float* fc1_b = (const float*)d_in[8];
    const float* bn1_g = (const float*)d_in[9];
    const float* bn1_b = (const float*)d_in[10];
    const float* fc2_w = (const float*)d_in[11];
    const float* fc2_b = (const float*)d_in[12];
    const float* bn2_g = (const float*)d_in[13];
    const float* bn2_b = (const float*)d_in[14];
    const float* fc3_w = (const float*)d_in[15];
    const float* fc3_b = (const float*)d_in[16];
    const float* bn3_g = (const float*)d_in[17];
    const float* bn3_b = (const float*)d_in[18];
    const float* out_w = (const float*)d_in[19];
    const float* out_b = (const float*)d_in[20];
    float* out = (float*)d_out;

    prep_all<<<918, 256>>>(w1, w2, w3, out_w, emb, fc1_w);

    cudaFuncSetAttribute(cin_main, cudaFuncAttributeMaxDynamicSharedMemorySize, SMEM_DYN);
    cin_main<<<BATCH / 2, NTHR, SMEM_DYN>>>(
        x, emb, lin_w, lin_b, fc1_b, bn1_g, bn1_b,
        fc2_w, fc2_b, bn2_g, bn2_b, fc3_w, fc3_b, bn3_g, bn3_b,
        out_w, out_b, out);
}

// round 10
// speedup vs baseline: 1.3895x; 1.2085x over previous
#include <cuda_runtime.h>
#include <cuda_bf16.h>
#include <math.h>
#include <stdint.h>

// ---------------------------------------------------------------------------
// Problem constants
// ---------------------------------------------------------------------------
#define BATCH 512
#define MF    48
#define DD    128
#define O1    68
#define O2    32
#define O3    24
#define NPAIR 1176          // 48*49/2 symmetric pairs
#define KDIAG 1224          // + 48 linear (diag) rows
#define KPAD  1280          // padded to 20 tiles of 64
#define NG    144           // GEMM N: 68 xk1 + 4 pad + 68 R' + 4 pad
#define NKT   20            // k-tiles of 64
#define KT    64
#define TILEB (NG*KT*2)     // 18432 bytes per B tile
#define XST   50            // x0 row stride (48 data + 1.0 + 0.0)
#define NTHR  512

// ---------------------------------------------------------------------------
// Device-global scratch (no allocation allowed)
// ---------------------------------------------------------------------------
__device__ unsigned int g_suv[KPAD];
__device__ float g_V3[O2 * MF];
__device__ __align__(16) __nv_bfloat16 g_Bt[NKT * NG * KT];  // packed+swizzled
__device__ float g_F[MF * MF * 64];                          // fc1 lookup

// ---------------------------------------------------------------------------
// Helpers
// ---------------------------------------------------------------------------
__device__ __forceinline__ void pair_decode(int t, int& u, int& v) {
    int k = 0, base = 0;
    while (t >= base + (MF - k)) { base += MF - k; ++k; }
    u = k; v = k + (t - base);
}

__device__ __forceinline__ uint32_t smem_u32(const void* p) {
    uint32_t a;
    asm("{ .reg .u64 t; cvta.to.shared.u64 t, %1; cvt.u32.u64 %0, t; }" : "=r"(a) : "l"(p));
    return a;
}

__device__ __forceinline__ void ldsm_x4(uint32_t& r0, uint32_t& r1,
                                        uint32_t& r2, uint32_t& r3, uint32_t addr) {
    asm volatile("ldmatrix.sync.aligned.m8n8.x4.shared.b16 {%0,%1,%2,%3}, [%4];"
                 : "=r"(r0), "=r"(r1), "=r"(r2), "=r"(r3) : "r"(addr));
}

__device__ __forceinline__ void mma16816(float* c, uint32_t a0, uint32_t a1,
                                         uint32_t a2, uint32_t a3,
                                         uint32_t b0, uint32_t b1) {
    asm volatile(
        "mma.sync.aligned.m16n8k16.row.col.f32.bf16.bf16.f32 "
        "{%0,%1,%2,%3}, {%4,%5,%6,%7}, {%8,%9}, {%0,%1,%2,%3};"
        : "+f"(c[0]), "+f"(c[1]), "+f"(c[2]), "+f"(c[3])
        : "r"(a0), "r"(a1), "r"(a2), "r"(a3), "r"(b0), "r"(b1));
}

__device__ __forceinline__ uint32_t h2mul(__nv_bfloat16 ax, __nv_bfloat16 ay,
                                          __nv_bfloat16 bx, __nv_bfloat16 by) {
    __nv_bfloat162 pa, pb;
    pa.x = ax; pa.y = ay; pb.x = bx; pb.y = by;
    __nv_bfloat162 r = __hmul2(pa, pb);
    return *reinterpret_cast<uint32_t*>(&r);
}

__device__ __forceinline__ void cp16(uint32_t dst, const void* src) {
    asm volatile("cp.async.cg.shared.global [%0], [%1], 16;" :: "r"(dst), "l"(src));
}
#define CP_COMMIT() asm volatile("cp.async.commit_group;" ::: "memory")
#define CP_WAIT0()  asm volatile("cp.async.wait_group 0;" ::: "memory")

// ---------------------------------------------------------------------------
// prep0 (199 blocks): suv table, V3, fc1 lookup table
// ---------------------------------------------------------------------------
__global__ void prep0(const float* __restrict__ w3, const float* __restrict__ out_w,
                      const float* __restrict__ emb, const float* __restrict__ fc1_w) {
    __shared__ float sf[1536 + 8192];
    const int tid = threadIdx.x;
    const int b   = blockIdx.x;

    if (b < 6) {                       // suv
        int gid = b * 256 + tid;
        if (gid < KPAD) {
            int u, v;
            if (gid < NPAIR)      { pair_decode(gid, u, v); }
            else if (gid < KDIAG) { u = gid - NPAIR; v = 48; }
            else                  { u = 49; v = 49; }
            g_suv[gid] = (unsigned)u | ((unsigned)v << 16);
        }
        return;
    }
    if (b == 6) {                      // V3
        for (int i = tid; i < O2 * MF; i += 256) {
            float s = 0.f;
            #pragma unroll
            for (int o = 0; o < O3; ++o) s += w3[i * O3 + o] * out_w[125 + o];
            g_V3[i] = s;
        }
        return;
    }
    // F table: j = field, q = m-quarter (12 rows)
    const int fb = b - 7;
    const int j = fb >> 2, q = fb & 3;
    float* se = sf;
    float* sw = sf + 1536;
    for (int i = tid; i < 1536; i += 256) se[i] = emb[q * 1536 + i];
    for (int i = tid; i < 8192; i += 256) sw[i] = fc1_w[j * 8192 + i];
    __syncthreads();
    #pragma unroll
    for (int t = 0; t < 3; ++t) {
        int o = t * 256 + tid;
        int m = o >> 6, c = o & 63;
        float s = 0.f;
        #pragma unroll 8
        for (int d = 0; d < DD; ++d) s += se[m * DD + d] * sw[d * 64 + c];
        g_F[((j * MF + q * 12 + m) << 6) + c] = s;
    }
}

// ---------------------------------------------------------------------------
// prep1 (652 blocks): pack B tiles.
//   [0,380):   n in [0,72) u [140,144)  — wsym + pad zeros (elementwise)
//   [380,652): n = 72+a — Tq rows, smem-tiled (stage w2 slice + V3 once)
// ---------------------------------------------------------------------------
__global__ void prep1(const float* __restrict__ w1, const float* __restrict__ w2,
                      const float* __restrict__ out_w) {
    __shared__ float sV[O2 * MF];      // 1536
    __shared__ float sw2[MF * O2];     // 1536
    __shared__ float sow[O2];
    const int tid = threadIdx.x;
    const int b   = blockIdx.x;

    if (b < 380) {
        int idx = b * 256 + tid;       // < 76*64*20 = 97280
        int t = idx / (76 * 64);
        int r = idx - t * (76 * 64);
        int nn = r >> 6, kk = r & 63;
        int n = (nn < 72) ? nn : (68 + nn);          // [0,72) -> n, 72..75 -> 140..143
        int k = t * 64 + kk;
        float val = 0.f;
        if (n < O1 && k < NPAIR) {
            int u, v; pair_decode(k, u, v);
            val = w1[(u * MF + v) * O1 + n];
            if (u < v) val += w1[(v * MF + u) * O1 + n];
        }
        int chunk = kk >> 3;
        int off = t * TILEB + n * 128 + ((chunk ^ (n & 7)) << 4) + ((kk & 7) << 1);
        *(__nv_bfloat16*)((char*)g_Bt + off) = __float2bfloat16_rn(val);
        return;
    }

    // Tq rows: a = field-out index, quarter of K
    const int bb = b - 380;
    const int a = bb >> 2, q = bb & 3;
    const int n = 72 + a;
    for (int i = tid; i < O2 * MF; i += 256) sV[i] = g_V3[i];
    for (int i = tid; i < MF * O2; i += 256) sw2[i] = w2[a * (MF * O2) + i];
    if (tid < O2) sow[tid] = out_w[25 + O1 + tid];
    __syncthreads();

    #pragma unroll
    for (int e = tid; e < 320; e += 256) {
        int k = q * 320 + e;
        float val = 0.f;
        if (k < NPAIR) {
            int u, v; pair_decode(k, u, v);
            float s = 0.f;
            const float* r1 = sw2 + u * O2;
            #pragma unroll 8
            for (int k2 = 0; k2 < O2; ++k2) s += r1[k2] * sV[k2 * MF + v];
            if (u < v) {
                const float* r2 = sw2 + v * O2;
                #pragma unroll 8
                for (int k2 = 0; k2 < O2; ++k2) s += r2[k2] * sV[k2 * MF + u];
            }
            val = s;
        } else if (k < KDIAG) {
            int m = k - NPAIR;
            float s = 0.f;
            const float* r1 = sw2 + m * O2;
            #pragma unroll 8
            for (int k2 = 0; k2 < O2; ++k2) s += r1[k2] * sow[k2];
            val = s;
        }
        int t = k >> 6, kk = k & 63;
        int chunk = kk >> 3;
        int off = t * TILEB + n * 128 + ((chunk ^ (n & 7)) << 4) + ((kk & 7) << 1);
        *(__nv_bfloat16*)((char*)g_Bt + off) = __float2bfloat16_rn(val);
    }
}

// ---------------------------------------------------------------------------
// Main fused kernel: one CTA per TWO batch rows, 512 threads / 16 warps.
// x0 stored bf16 (halved A-gen LDS bytes); products via HMUL2.
// ---------------------------------------------------------------------------
// dyn smem layout (bytes, from 1024-aligned base)
#define OFF_X0B   0                    // 2 * 128*50 bf16 = 25600
#define OFF_B     25600                // 2 * 18432 = 36864
#define OFF_SUV   62464                // 1280 u32  = 5120
#define OFF_OWP   67584                // 144 f32   = 576
#define OFF_XR    68160                // 2*48 int  = 384
#define OFF_D1    68544                // 2*64 f32
#define OFF_D2    69056                // 2*48 f32
#define OFF_D3    69440                // 2*24 f32
#define OFF_RED   69632                // 16 f32
#define SMEM_DYN  (69696 + 1024)

__global__ __launch_bounds__(NTHR, 1) void cin_main(
    const int*   __restrict__ x,     const float* __restrict__ emb,
    const float* __restrict__ lin_w, const float* __restrict__ lin_b,
    const float* __restrict__ fc1_b,
    const float* __restrict__ bn1_g, const float* __restrict__ bn1_b,
    const float* __restrict__ fc2_w, const float* __restrict__ fc2_b,
    const float* __restrict__ bn2_g, const float* __restrict__ bn2_b,
    const float* __restrict__ fc3_w, const float* __restrict__ fc3_b,
    const float* __restrict__ bn3_g, const float* __restrict__ bn3_b,
    const float* __restrict__ out_w, const float* __restrict__ out_b,
    float* __restrict__ out)
{
    extern __shared__ char smraw[];
    char* sm = (char*)(((uintptr_t)smraw + 1023) & ~(uintptr_t)1023);
    __nv_bfloat16* x0b = (__nv_bfloat16*)(sm + OFF_X0B);  // [2][128][50]
    unsigned int* ssuv = (unsigned int*)(sm + OFF_SUV);
    float*        owp  = (float*)(sm + OFF_OWP);
    int*          xr   = (int*)(sm + OFF_XR);
    float*        d1s  = (float*)(sm + OFF_D1);
    float*        d2s  = (float*)(sm + OFF_D2);
    float*        d3s  = (float*)(sm + OFF_D3);
    float*        red  = (float*)(sm + OFF_RED);

    const int tid  = threadIdx.x;
    const int lane = tid & 31;
    const int warp = tid >> 5;       // 0..15
    const uint32_t s32 = smem_u32(sm);

    if (tid < 2 * MF) xr[tid] = x[blockIdx.x * (2 * MF) + tid];
    for (int i = tid; i < NG; i += NTHR) owp[i] = (i < O1) ? out_w[25 + i] : 0.f;
    for (int i = tid; i < KPAD; i += NTHR) ssuv[i] = g_suv[i];
    __syncthreads();

    // gather both samples' x0 transposed (bf16): x0b[smp*6400 + d*50 + j]
    for (int i = tid; i < 2 * DD * XST; i += NTHR) {
        int smp = i / (DD * XST);
        int rr  = i - smp * (DD * XST);
        int d = rr / XST, j = rr - d * XST;
        float v;
        if (j < MF)       v = emb[(xr[smp * MF + j] << 7) + d];
        else if (j == 48) v = 1.0f;
        else              v = 0.0f;
        x0b[i] = __float2bfloat16_rn(v);
    }

    // prologue: cp.async B tile 0 into buf0
    for (int i = tid; i < TILEB / 16; i += NTHR)
        cp16(s32 + OFF_B + i * 16, (const char*)g_Bt + i * 16);
    CP_COMMIT();
    CP_WAIT0();
    __syncthreads();

    // per-warp fragment geometry: m-tile = warp>>1, sample = warp&1
    const int wsmp  = warp & 1;
    const int rbase = wsmp * 6400 + (((warp >> 1) * 16) + (lane >> 2)) * XST;
    const __nv_bfloat16* rA0 = x0b + rbase;
    const __nv_bfloat16* rA1 = rA0 + 8 * XST;
    const int kq    = (lane & 3) << 1;
    const int matq  = lane >> 3;
    const int nloc  = ((matq >= 2) ? 8 : 0) + (lane & 7);
    const int cksel = matq & 1;

    float acc[18][4];
    #pragma unroll
    for (int i = 0; i < 18; ++i)
        #pragma unroll
        for (int r = 0; r < 4; ++r) acc[i][r] = 0.f;

    for (int t = 0; t < NKT; ++t) {
        const int buf = t & 1;
        if (t < NKT - 1) {
            const char* src = (const char*)g_Bt + (t + 1) * TILEB;
            uint32_t dst = s32 + OFF_B + (buf ^ 1) * TILEB;
            for (int i = tid; i < TILEB / 16; i += NTHR)
                cp16(dst + i * 16, src + i * 16);
            CP_COMMIT();
        }
        const uint32_t Bb = s32 + OFF_B + buf * TILEB;
        const int k0 = t * 64;

        #pragma unroll
        for (int s = 0; s < 4; ++s) {
            const int ks = s << 4;
            const int kg = k0 + ks + kq;
            unsigned p0 = ssuv[kg],     p1 = ssuv[kg + 1];
            unsigned p8 = ssuv[kg + 8], p9 = ssuv[kg + 9];
            const int u0 = p0 & 0xFFFF, w0i = p0 >> 16;
            const int u1 = p1 & 0xFFFF, w1i = p1 >> 16;
            const int u8 = p8 & 0xFFFF, w8i = p8 >> 16;
            const int u9 = p9 & 0xFFFF, w9i = p9 >> 16;
            uint32_t a0 = h2mul(rA0[u0], rA0[u1], rA0[w0i], rA0[w1i]);
            uint32_t a1 = h2mul(rA1[u0], rA1[u1], rA1[w0i], rA1[w1i]);
            uint32_t a2 = h2mul(rA0[u8], rA0[u9], rA0[w8i], rA0[w9i]);
            uint32_t a3 = h2mul(rA1[u8], rA1[u9], rA1[w8i], rA1[w9i]);

            const int chunk = (ks >> 3) + cksel;
            #pragma unroll
            for (int q = 0; q < 9; ++q) {
                const int n = q * 16 + nloc;
                uint32_t baddr = Bb + n * 128 + (uint32_t)((chunk ^ (n & 7)) << 4);
                uint32_t b0, b1, b2, b3;
                ldsm_x4(b0, b1, b2, b3, baddr);
                mma16816(acc[2 * q],     a0, a1, a2, a3, b0, b1);
                mma16816(acc[2 * q + 1], a0, a1, a2, a3, b2, b3);
            }
        }
        if (t < NKT - 1) CP_WAIT0();
        __syncthreads();
    }

    // ---- epilogue straight from accumulator registers ----
    float part = 0.f;
    #pragma unroll
    for (int nt = 0; nt < 9; ++nt) {
        const float w0 = owp[nt * 8 + kq];
        const float w1v = owp[nt * 8 + kq + 1];
        #pragma unroll
        for (int r = 0; r < 4; ++r) {
            float wv = (r & 1) ? w1v : w0;
            float xa = acc[nt][r];
            part += xa * acc[nt + 9][r] + wv * xa;
        }
    }
    #pragma unroll
    for (int off = 16; off; off >>= 1)
        part += __shfl_xor_sync(0xffffffffu, part, off);
    if (lane == 0) red[warp] = part;

    // ---- deep MLP (fp32 exact): half-block per sample ----
    const int smp = tid >> 8;        // 0 or 1
    const int t1  = tid & 255;
    const int* xrs = xr + smp * MF;
    const float invs = rsqrtf(1.0f + 1e-3f);
    __syncthreads();
    if (t1 < 64) {
        float a = fc1_b[t1];
        #pragma unroll
        for (int j = 0; j < MF; ++j) a += g_F[((j * MF + xrs[j]) << 6) + t1];
        a = fmaxf(a, 0.f);
        d1s[smp * 64 + t1] = bn1_g[t1] * a * invs + bn1_b[t1];
    }
    __syncthreads();
    if (t1 < 48) {
        float a = fc2_b[t1];
        const float* d1 = d1s + smp * 64;
        #pragma unroll 8
        for (int i = 0; i < 64; ++i) a += d1[i] * fc2_w[i * 48 + t1];
        a = tanhf(a);
        d2s[smp * 48 + t1] = bn2_g[t1] * a * invs + bn2_b[t1];
    }
    __syncthreads();
    if (t1 < 24) {
        float a = fc3_b[t1];
        const float* d2 = d2s + smp * 48;
        #pragma unroll 8
        for (int i = 0; i < 48; ++i) a += d2[i] * fc3_w[i * 24 + t1];
        a = tanhf(a);
        d3s[smp * 24 + t1] = bn3_g[t1] * a * invs + bn3_b[t1];
    }
    __syncthreads();

    if (t1 == 0) {
        float lg = out_b[0];
        #pragma unroll
        for (int w = 0; w < 8; ++w) lg += red[2 * w + smp];
        const float* d3 = d3s + smp * 24;
        #pragma unroll
        for (int c = 0; c < 24; ++c) lg += d3[c] * out_w[c];
        float sl = lin_b[0];
        #pragma unroll
        for (int j = 0; j < MF; ++j) sl += (float)xrs[j] * lin_w[j];
        lg += tanhf(sl) * out_w[24];
        out[blockIdx.x * 2 + smp] = 1.0f / (1.0f + expf(-lg));
    }
}

// ---------------------------------------------------------------------------
// Launch
// ---------------------------------------------------------------------------
extern "C" void kernel_launch(void* const* d_in, const int* in_sizes, int n_in,
                              void* d_out, int out_size)
{
    const int*   x     = (const int*)  d_in[0];
    const float* emb   = (const float*)d_in[1];
    const float* w1    = (const float*)d_in[2];
    const float* w2    = (const float*)d_in[3];
    const float* w3    = (const float*)d_in[4];
    const float* lin_w = (const float*)d_in[5];
    const float* lin_b = (const float*)d_in[6];
    const float* fc1_w = (const float*)d_in[7];
    const float* fc1_b = (const float*)d_in[8];
    const float* bn1_g = (const float*)d_in[9];
    const float* bn1_b = (const float*)d_in[10];
    const float* fc2_w = (const float*)d_in[11];
    const float* fc2_b = (const float*)d_in[12];
    const float* bn2_g = (const float*)d_in[13];
    const float* bn2_b = (const float*)d_in[14];
    const float* fc3_w = (const float*)d_in[15];
    const float* fc3_b = (const float*)d_in[16];
    const float* bn3_g = (const float*)d_in[17];
    const float* bn3_b = (const float*)d_in[18];
    const float* out_w = (const float*)d_in[19];
    const float* out_b = (const float*)d_in[20];
    float* out = (float*)d_out;

    prep0<<<199, 256>>>(w3, out_w, emb, fc1_w);
    prep1<<<652, 256>>>(w1, w2, out_w);

    cudaFuncSetAttribute(cin_main, cudaFuncAttributeMaxDynamicSharedMemorySize, SMEM_DYN);
    cin_main<<<BATCH / 2, NTHR, SMEM_DYN>>>(
        x, emb, lin_w, lin_b, fc1_b, bn1_g, bn1_b,
        fc2_w, fc2_b, bn2_g, bn2_b, fc3_w, fc3_b, bn3_g, bn3_b,
        out_w, out_b, out);
}